// round 4
// baseline (speedup 1.0000x reference)
#include <cuda_runtime.h>

// Scratch: __device__ globals only (no allocation allowed).
#define MAXV (1 << 19)      // 512k vertices (actual V ~ 185k)
#define KMAX 16             // adjacency storage slots per vertex
#define KUNROLL 8           // fully-unrolled fast path (covers valence <= 8)

__device__ float4 g_x[MAXV];            // positions (iter-1 input)
__device__ float4 g_y[MAXV];            // positions after iter 1
__device__ int    g_cnt[MAXV];          // degree / slot counter
__device__ int    g_adj[KMAX * MAXV];   // slot-major adjacency (coalesced over v)

// ---------------------------------------------------------------------------
// Fused: pack v -> g_x + zero counters (first gV blocks); faces int->float
// copy (remaining blocks, int4-vectorized).
__global__ void k_repack_faces(const float* __restrict__ v, int V, int gV,
                               const int* __restrict__ faces,
                               float* __restrict__ fout, int nF3) {
    if ((int)blockIdx.x < gV) {
        int i = blockIdx.x * blockDim.x + threadIdx.x;
        if (i < V) {
            g_x[i] = make_float4(v[3 * i], v[3 * i + 1], v[3 * i + 2], 0.f);
            g_cnt[i] = 0;
        }
    } else {
        int t = (blockIdx.x - gV) * blockDim.x + threadIdx.x;
        int base = t * 4;
        if (base + 4 <= nF3) {
            int4 f = *(const int4*)(faces + base);
            *(float4*)(fout + base) =
                make_float4((float)f.x, (float)f.y, (float)f.z, (float)f.w);
        } else if (base < nF3) {
            for (int j = base; j < nF3; ++j) fout[j] = (float)faces[j];
        }
    }
}

// Build adjacency: each edge registers itself at both endpoints.
__global__ void k_fill(const int2* __restrict__ edges, int E) {
    int i = blockIdx.x * blockDim.x + threadIdx.x;
    if (i < E) {
        int2 e = edges[i];
        int sa = atomicAdd(&g_cnt[e.x], 1) & (KMAX - 1);
        int sb = atomicAdd(&g_cnt[e.y], 1) & (KMAX - 1);
        g_adj[sa * MAXV + e.x] = e.y;
        g_adj[sb * MAXV + e.y] = e.x;
    }
}

// Pure gather with maximal MLP: all adjacency slots loaded up front
// (unconditional, coalesced), then all random position loads issued as a
// single predicated front batch — no serial tail for valence <= KUNROLL.
template <bool FINAL>
__global__ void k_gather(float* __restrict__ out, int V) {
    int v = blockIdx.x * blockDim.x + threadIdx.x;
    if (v >= V) return;
    int d = g_cnt[v];
    if (d > KMAX) d = KMAX;
    const float4* __restrict__ src = FINAL ? g_y : g_x;

    // Stage 1: all adjacency slots (beyond d: garbage values, never used).
    int nb[KUNROLL];
#pragma unroll
    for (int j = 0; j < KUNROLL; ++j)
        nb[j] = g_adj[j * MAXV + v];

    // Stage 2: predicated random position loads, all independent.
    float sx = 0.f, sy = 0.f, sz = 0.f;
#pragma unroll
    for (int j = 0; j < KUNROLL; ++j) {
        if (j < d) {
            float4 p = __ldg(&src[nb[j]]);
            sx += p.x; sy += p.y; sz += p.z;
        }
    }
    // Rare high-valence tail.
    for (int j = KUNROLL; j < d; ++j) {
        float4 p = __ldg(&src[g_adj[j * MAXV + v]]);
        sx += p.x; sy += p.y; sz += p.z;
    }

    float inv = 1.0f / fmaxf((float)d, 1.0f);
    if (FINAL) {
        out[3 * v + 0] = sx * inv;
        out[3 * v + 1] = sy * inv;
        out[3 * v + 2] = sz * inv;
    } else {
        g_y[v] = make_float4(sx * inv, sy * inv, sz * inv, 0.f);
    }
}

// ---------------------------------------------------------------------------
extern "C" void kernel_launch(void* const* d_in, const int* in_sizes, int n_in,
                              void* d_out, int out_size) {
    const float* v     = (const float*)d_in[0];   // [1,V,3] f32
    const int2*  edges = (const int2*)d_in[1];    // [E,2]   i32
    const int*   faces = (const int*)d_in[2];     // [1,F,3] i32

    const int V   = in_sizes[0] / 3;
    const int E   = in_sizes[1] / 2;
    const int nF3 = in_sizes[2];

    float* out  = (float*)d_out;
    float* fout = out + 3 * V;
    const bool do_faces = (out_size >= 3 * V + nF3);

    const int T = 256;
    const int gV = (V + T - 1) / T;
    const int gE = (E + T - 1) / T;
    const int gF = do_faces ? ((nF3 + 4 * T - 1) / (4 * T)) : 0;

    k_repack_faces<<<gV + gF, T>>>(v, V, gV, faces, fout, do_faces ? nF3 : 0);
    k_fill<<<gE, T>>>(edges, E);
    k_gather<false><<<gV, T>>>(nullptr, V);   // iter 1: g_x -> g_y
    k_gather<true><<<gV, T>>>(out, V);        // iter 2: g_y -> out
}

// round 8
// speedup vs baseline: 1.0061x; 1.0061x over previous
#include <cuda_runtime.h>

// Scratch: __device__ globals only (no allocation allowed).
#define MAXV (1 << 19)      // 512k vertices (actual V ~ 185k)
#define KMAX 16             // adjacency storage slots per vertex
#define KUNROLL 8           // fast path covers valence <= 8 (4 per half-thread)

__device__ float4 g_x[MAXV];            // positions (iter-1 input)
__device__ float4 g_y[MAXV];            // positions after iter 1
__device__ int    g_cnt[MAXV];          // degree / slot counter
__device__ int    g_adj[KMAX * MAXV];   // slot-major adjacency (coalesced over v)

// ---------------------------------------------------------------------------
// Fused: pack v -> g_x + zero counters (first gV blocks); faces int->float
// copy (remaining blocks, int4-vectorized).
__global__ void k_repack_faces(const float* __restrict__ v, int V, int gV,
                               const int* __restrict__ faces,
                               float* __restrict__ fout, int nF3) {
    if ((int)blockIdx.x < gV) {
        int i = blockIdx.x * blockDim.x + threadIdx.x;
        if (i < V) {
            g_x[i] = make_float4(v[3 * i], v[3 * i + 1], v[3 * i + 2], 0.f);
            g_cnt[i] = 0;
        }
    } else {
        int t = (blockIdx.x - gV) * blockDim.x + threadIdx.x;
        int base = t * 4;
        if (base + 4 <= nF3) {
            int4 f = *(const int4*)(faces + base);
            *(float4*)(fout + base) =
                make_float4((float)f.x, (float)f.y, (float)f.z, (float)f.w);
        } else if (base < nF3) {
            for (int j = base; j < nF3; ++j) fout[j] = (float)faces[j];
        }
    }
}

// Build adjacency: each edge registers itself at both endpoints.
__global__ void k_fill(const int2* __restrict__ edges, int E) {
    int i = blockIdx.x * blockDim.x + threadIdx.x;
    if (i < E) {
        int2 e = edges[i];
        int sa = atomicAdd(&g_cnt[e.x], 1) & (KMAX - 1);
        int sb = atomicAdd(&g_cnt[e.y], 1) & (KMAX - 1);
        g_adj[sa * MAXV + e.x] = e.y;
        g_adj[sb * MAXV + e.y] = e.x;
    }
}

// Gather with 2 threads per vertex (adjacent lanes). Each half-thread handles
// 4 adjacency slots; partial sums combined via shfl_xor(1). Doubles resident
// warps (occupancy was grid-limited at 57%) and halves per-thread load chains.
template <bool FINAL>
__global__ void k_gather2(float* __restrict__ out, int V) {
    int idx = blockIdx.x * blockDim.x + threadIdx.x;
    int v = idx >> 1;
    int half = idx & 1;
    if (v >= V) return;
    int d = g_cnt[v];
    if (d > KMAX) d = KMAX;
    const float4* __restrict__ src = FINAL ? g_y : g_x;

    // This half-thread's 4 slots: j = half*4 + 0..3
    int jbase = half * 4;
    int nb[4];
#pragma unroll
    for (int j = 0; j < 4; ++j)
        nb[j] = g_adj[(jbase + j) * MAXV + v];

    float sx = 0.f, sy = 0.f, sz = 0.f;
#pragma unroll
    for (int j = 0; j < 4; ++j) {
        if (jbase + j < d) {
            float4 p = __ldg(&src[nb[j]]);
            sx += p.x; sy += p.y; sz += p.z;
        }
    }
    // Rare high-valence tail (handled by half 0).
    if (half == 0) {
        for (int j = KUNROLL; j < d; ++j) {
            float4 p = __ldg(&src[g_adj[j * MAXV + v]]);
            sx += p.x; sy += p.y; sz += p.z;
        }
    }

    // Combine the two halves (adjacent lanes).
    sx += __shfl_xor_sync(0xffffffffu, sx, 1);
    sy += __shfl_xor_sync(0xffffffffu, sy, 1);
    sz += __shfl_xor_sync(0xffffffffu, sz, 1);

    if (half == 0) {
        float inv = 1.0f / fmaxf((float)d, 1.0f);
        if (FINAL) {
            out[3 * v + 0] = sx * inv;
            out[3 * v + 1] = sy * inv;
            out[3 * v + 2] = sz * inv;
        } else {
            g_y[v] = make_float4(sx * inv, sy * inv, sz * inv, 0.f);
        }
    }
}

// ---------------------------------------------------------------------------
extern "C" void kernel_launch(void* const* d_in, const int* in_sizes, int n_in,
                              void* d_out, int out_size) {
    const float* v     = (const float*)d_in[0];   // [1,V,3] f32
    const int2*  edges = (const int2*)d_in[1];    // [E,2]   i32
    const int*   faces = (const int*)d_in[2];     // [1,F,3] i32

    const int V   = in_sizes[0] / 3;
    const int E   = in_sizes[1] / 2;
    const int nF3 = in_sizes[2];

    float* out  = (float*)d_out;
    float* fout = out + 3 * V;
    const bool do_faces = (out_size >= 3 * V + nF3);

    const int T = 256;
    const int gV  = (V + T - 1) / T;
    const int gE  = (E + T - 1) / T;
    const int g2V = (2 * V + T - 1) / T;
    const int gF  = do_faces ? ((nF3 + 4 * T - 1) / (4 * T)) : 0;

    k_repack_faces<<<gV + gF, T>>>(v, V, gV, faces, fout, do_faces ? nF3 : 0);
    k_fill<<<gE, T>>>(edges, E);
    k_gather2<false><<<g2V, T>>>(nullptr, V);   // iter 1: g_x -> g_y
    k_gather2<true><<<g2V, T>>>(out, V);        // iter 2: g_y -> out
}